// round 5
// baseline (speedup 1.0000x reference)
#include <cuda_runtime.h>
#include <cuda_bf16.h>

// Problem constants (fixed by the reference setup)
constexpr int B        = 16;
constexpr int H        = 16;
constexpr int D        = 128;
constexpr int BS       = 16;    // tokens per physical KV block
constexpr int BPS      = 128;   // blocks per sequence
constexpr int NSPLIT   = 8;
constexpr int CHUNK    = 256;   // tokens per split (NSPLIT*CHUNK = 2048)
constexpr int NW       = 8;     // warps per CTA
constexpr int THREADS  = NW * 32;

// Scratch for split-KV partials (no cudaMalloc allowed)
__device__ float g_part_acc[B * H * NSPLIT * D];   // 1 MB
__device__ float g_part_ml [B * H * NSPLIT * 2];   // (m, l) per partial

// ---------------------------------------------------------------------------
// Kernel 1: per-(b,h,split) partial attention, single-pass online softmax.
// Warp per 2 tokens/iter: K+V float4 loads for both tokens issued together
// (MLP=4/warp), full-butterfly dot reduce (all lanes get score), register-
// resident (m, l, acc). Cross-warp merge in SMEM at the end.
// ---------------------------------------------------------------------------
__global__ __launch_bounds__(THREADS)
void pa_split_kernel(const float* __restrict__ q,
                     const float* __restrict__ kc,
                     const float* __restrict__ vc,
                     const int*   __restrict__ bt,
                     const int*   __restrict__ cl)
{
    __shared__ int    sblk[CHUNK / BS];
    __shared__ float  sm[NW], sl[NW];
    __shared__ float4 wacc4[NW][D / 4];   // 4 KB

    const int tid  = threadIdx.x;
    const int lane = tid & 31;
    const int wid  = tid >> 5;

    const int s  = blockIdx.x & (NSPLIT - 1);
    const int bh = blockIdx.x >> 3;          // b*H + h
    const int b  = bh >> 4;
    const int h  = bh & 15;

    const int ctx   = cl[b];
    const int t0    = s * CHUNK;
    const int pbase = bh * NSPLIT + s;

    int n = ctx - t0;
    if (n > CHUNK) n = CHUNK;

    if (n <= 0) {
        // Inactive split: deterministic zero partial.
        if (tid < D) g_part_acc[pbase * D + tid] = 0.0f;
        if (tid == 0) {
            g_part_ml[2 * pbase + 0] = -3.0e38f;
            g_part_ml[2 * pbase + 1] = 0.0f;
        }
        return;
    }

    if (tid < CHUNK / BS)
        sblk[tid] = bt[b * BPS + s * (CHUNK / BS) + tid];

    const float4 q4 = reinterpret_cast<const float4*>(q + (size_t)bh * D)[lane];
    __syncthreads();

    const float scale = 0.08838834764831845f;   // 1/sqrt(128)

    float  m = -3.0e38f;
    float  l = 0.0f;
    float4 acc = make_float4(0.f, 0.f, 0.f, 0.f);

    // Two tokens per warp per iteration; K+V loads front-batched.
    for (int t = 2 * wid; t < n; t += 2 * NW) {
        const int  t1   = t + 1;
        const bool has2 = (t1 < n);

        const size_t off1 = (((size_t)sblk[t >> 4] * BS + (t & 15)) * H + h) * D;
        const float4 k1 = reinterpret_cast<const float4*>(kc + off1)[lane];
        const float4 v1 = reinterpret_cast<const float4*>(vc + off1)[lane];

        float4 k2 = make_float4(0.f, 0.f, 0.f, 0.f);
        float4 v2 = make_float4(0.f, 0.f, 0.f, 0.f);
        if (has2) {
            const size_t off2 = (((size_t)sblk[t1 >> 4] * BS + (t1 & 15)) * H + h) * D;
            k2 = reinterpret_cast<const float4*>(kc + off2)[lane];
            v2 = reinterpret_cast<const float4*>(vc + off2)[lane];
        }

        float d1 = k1.x * q4.x + k1.y * q4.y + k1.z * q4.z + k1.w * q4.w;
        float d2 = k2.x * q4.x + k2.y * q4.y + k2.z * q4.z + k2.w * q4.w;

        // Full butterfly: every lane ends with the complete dot product.
        #pragma unroll
        for (int mask = 16; mask; mask >>= 1) {
            d1 += __shfl_xor_sync(0xffffffffu, d1, mask);
            d2 += __shfl_xor_sync(0xffffffffu, d2, mask);
        }

        d1 *= scale;
        d2 = has2 ? d2 * scale : -3.0e38f;

        const float mn   = fmaxf(m, fmaxf(d1, d2));
        const float corr = __expf(m - mn);
        const float p1   = __expf(d1 - mn);
        const float p2   = has2 ? __expf(d2 - mn) : 0.0f;

        l = l * corr + p1 + p2;
        acc.x = acc.x * corr + p1 * v1.x + p2 * v2.x;
        acc.y = acc.y * corr + p1 * v1.y + p2 * v2.y;
        acc.z = acc.z * corr + p1 * v1.z + p2 * v2.z;
        acc.w = acc.w * corr + p1 * v1.w + p2 * v2.w;
        m = mn;
    }

    // ---- Cross-warp merge -----------------------------------------------------
    if (lane == 0) { sm[wid] = m; sl[wid] = l; }
    wacc4[wid][lane] = acc;
    __syncthreads();

    // Warps that processed no tokens have m=-3e38, l=0, acc=0 -> weight 0.
    float M = -3.0e38f;
    #pragma unroll
    for (int w = 0; w < NW; ++w) M = fmaxf(M, sm[w]);

    if (tid < D) {
        const float* wf = reinterpret_cast<const float*>(wacc4);
        float o = 0.0f;
        #pragma unroll
        for (int w = 0; w < NW; ++w)
            o += wf[w * D + tid] * __expf(sm[w] - M);
        g_part_acc[pbase * D + tid] = o;
    }
    if (tid == 0) {
        float L = 0.0f;
        #pragma unroll
        for (int w = 0; w < NW; ++w)
            L += sl[w] * __expf(sm[w] - M);
        g_part_ml[2 * pbase + 0] = M;
        g_part_ml[2 * pbase + 1] = L;
    }
}

// ---------------------------------------------------------------------------
// Kernel 2: combine NSPLIT partials per (b,h) via log-sum-exp.
// ---------------------------------------------------------------------------
__global__ __launch_bounds__(D)
void pa_combine_kernel(float* __restrict__ out)
{
    const int bh = blockIdx.x;
    const int d  = threadIdx.x;

    float lm[NSPLIT], ll[NSPLIT];
    float M = -3.4e38f;
    #pragma unroll
    for (int s = 0; s < NSPLIT; ++s) {
        lm[s] = g_part_ml[2 * (bh * NSPLIT + s) + 0];
        ll[s] = g_part_ml[2 * (bh * NSPLIT + s) + 1];
        M = fmaxf(M, lm[s]);
    }

    float L = 0.0f, o = 0.0f;
    #pragma unroll
    for (int s = 0; s < NSPLIT; ++s) {
        const float f = __expf(lm[s] - M);
        L += ll[s] * f;
        o += g_part_acc[(bh * NSPLIT + s) * D + d] * f;
    }
    out[bh * D + d] = o / L;
}

extern "C" void kernel_launch(void* const* d_in, const int* in_sizes, int n_in,
                              void* d_out, int out_size)
{
    const float* q  = (const float*)d_in[0];
    const float* kc = (const float*)d_in[1];
    const float* vc = (const float*)d_in[2];
    const int*   bt = (const int*)d_in[3];
    const int*   cl = (const int*)d_in[4];
    float* out = (float*)d_out;

    pa_split_kernel<<<B * H * NSPLIT, THREADS>>>(q, kc, vc, bt, cl);
    pa_combine_kernel<<<B * H, D>>>(out);
}

// round 6
// speedup vs baseline: 1.1806x; 1.1806x over previous
#include <cuda_runtime.h>
#include <cuda_bf16.h>

// Problem constants (fixed by the reference setup)
constexpr int B        = 16;
constexpr int H        = 16;
constexpr int D        = 128;
constexpr int BS       = 16;    // tokens per physical KV block
constexpr int BPS      = 128;   // blocks per sequence
constexpr int NSPLIT   = 8;
constexpr int CHUNK    = 256;   // tokens per split (NSPLIT*CHUNK = 2048)
constexpr int NW       = 8;     // warps per CTA
constexpr int THREADS  = NW * 32;
constexpr int TPW      = 4;     // tokens per warp per iteration (MLP=4)

// Scratch for split-KV partials (no cudaMalloc allowed)
__device__ float g_part_acc[B * H * NSPLIT * D];   // 1 MB
__device__ float g_part_ml [B * H * NSPLIT * 2];   // (m, l) per partial

__device__ __forceinline__ float warp_sum(float v) {
    v += __shfl_xor_sync(0xffffffffu, v, 16);
    v += __shfl_xor_sync(0xffffffffu, v, 8);
    v += __shfl_xor_sync(0xffffffffu, v, 4);
    v += __shfl_xor_sync(0xffffffffu, v, 2);
    v += __shfl_xor_sync(0xffffffffu, v, 1);
    return v;
}
__device__ __forceinline__ float warp_max(float v) {
    v = fmaxf(v, __shfl_xor_sync(0xffffffffu, v, 16));
    v = fmaxf(v, __shfl_xor_sync(0xffffffffu, v, 8));
    v = fmaxf(v, __shfl_xor_sync(0xffffffffu, v, 4));
    v = fmaxf(v, __shfl_xor_sync(0xffffffffu, v, 2));
    v = fmaxf(v, __shfl_xor_sync(0xffffffffu, v, 1));
    return v;
}

// ---------------------------------------------------------------------------
// Kernel 1: per-(b,h,split) partial attention, two-pass, MLP=4 per warp.
// All K/V loads are UNGUARDED (block_tables is fully populated, so addresses
// past ctx are valid); only the scores are masked. sc[] and sblk[] are padded
// so the 4-token group overrun (t+3) stays in-bounds.
// ---------------------------------------------------------------------------
__global__ __launch_bounds__(THREADS)
void pa_split_kernel(const float* __restrict__ q,
                     const float* __restrict__ kc,
                     const float* __restrict__ vc,
                     const int*   __restrict__ bt,
                     const int*   __restrict__ cl)
{
    __shared__ float  sc[CHUNK + TPW];        // padded score buffer
    __shared__ float4 wacc4[NW][D / 4];       // 4 KB
    __shared__ int    sblk[CHUNK / BS + 1];   // padded block ids
    __shared__ float  red[NW];
    __shared__ float  s_m;

    const int tid  = threadIdx.x;
    const int lane = tid & 31;
    const int wid  = tid >> 5;

    const int s  = blockIdx.x & (NSPLIT - 1);
    const int bh = blockIdx.x >> 3;          // b*H + h
    const int b  = bh >> 4;
    const int h  = bh & 15;

    const int ctx   = cl[b];
    const int t0    = s * CHUNK;
    const int pbase = bh * NSPLIT + s;

    int n = ctx - t0;
    if (n > CHUNK) n = CHUNK;

    if (n <= 0) {
        // Inactive split: deterministic zero partial.
        if (tid < D) g_part_acc[pbase * D + tid] = 0.0f;
        if (tid == 0) {
            g_part_ml[2 * pbase + 0] = -3.0e38f;
            g_part_ml[2 * pbase + 1] = 0.0f;
        }
        return;
    }

    // Block ids for this chunk, +1 pad entry (clamped to a valid table slot).
    if (tid < CHUNK / BS + 1) {
        int idx = s * (CHUNK / BS) + tid;
        if (idx > BPS - 1) idx = BPS - 1;
        sblk[tid] = bt[b * BPS + idx];
    }
    // Zero the pad region of the score buffer (so pass-2 overrun reads p=0).
    if (tid < TPW) sc[CHUNK + tid] = 0.0f;

    const float4 q4 = reinterpret_cast<const float4*>(q + (size_t)bh * D)[lane];
    __syncthreads();

    const float scale = 0.08838834764831845f;   // 1/sqrt(128)

    // ---- Pass 1: scores, 4 tokens/warp/iter, unguarded loads ---------------
    for (int t = TPW * wid; t < n; t += TPW * NW) {
        float4 kk[TPW];
        #pragma unroll
        for (int j = 0; j < TPW; ++j) {
            const int tt = t + j;
            const size_t off = (((size_t)sblk[tt >> 4] * BS + (tt & 15)) * H + h) * D;
            kk[j] = reinterpret_cast<const float4*>(kc + off)[lane];
        }

        float d[TPW];
        #pragma unroll
        for (int j = 0; j < TPW; ++j)
            d[j] = kk[j].x * q4.x + kk[j].y * q4.y + kk[j].z * q4.z + kk[j].w * q4.w;

        // Four interleaved butterfly reductions (ILP hides shfl latency).
        #pragma unroll
        for (int mask = 16; mask; mask >>= 1) {
            #pragma unroll
            for (int j = 0; j < TPW; ++j)
                d[j] += __shfl_xor_sync(0xffffffffu, d[j], mask);
        }

        if (lane == 0) {
            #pragma unroll
            for (int j = 0; j < TPW; ++j)
                if (t + j < n) sc[t + j] = d[j] * scale;
        }
    }
    __syncthreads();

    // ---- Block softmax over the chunk ---------------------------------------
    float v = (tid < n) ? sc[tid] : -3.0e38f;
    float m = warp_max(v);
    if (lane == 0) red[wid] = m;
    __syncthreads();
    if (wid == 0) {
        float x = (lane < NW) ? red[lane] : -3.0e38f;
        x = warp_max(x);
        if (lane == 0) s_m = x;
    }
    __syncthreads();
    const float M = s_m;

    const float p = (tid < n) ? __expf(v - M) : 0.0f;
    sc[tid] = p;                      // invalid slots get 0 -> pass 2 unguarded
    float l = warp_sum(p);
    if (lane == 0) red[wid] = l;
    __syncthreads();

    // ---- Pass 2: weighted V accumulation, 4 tokens/warp/iter, unguarded -----
    float4 acc = make_float4(0.f, 0.f, 0.f, 0.f);
    for (int t = TPW * wid; t < n; t += TPW * NW) {
        float  pp[TPW];
        float4 vv[TPW];
        #pragma unroll
        for (int j = 0; j < TPW; ++j) pp[j] = sc[t + j];
        #pragma unroll
        for (int j = 0; j < TPW; ++j) {
            const int tt = t + j;
            const size_t off = (((size_t)sblk[tt >> 4] * BS + (tt & 15)) * H + h) * D;
            vv[j] = reinterpret_cast<const float4*>(vc + off)[lane];
        }
        #pragma unroll
        for (int j = 0; j < TPW; ++j) {
            acc.x += pp[j] * vv[j].x;
            acc.y += pp[j] * vv[j].y;
            acc.z += pp[j] * vv[j].z;
            acc.w += pp[j] * vv[j].w;
        }
    }
    wacc4[wid][lane] = acc;
    __syncthreads();

    if (tid < D) {
        const float* wf = reinterpret_cast<const float*>(wacc4);
        float o = 0.0f;
        #pragma unroll
        for (int w = 0; w < NW; ++w) o += wf[w * D + tid];
        g_part_acc[pbase * D + tid] = o;
    }
    if (tid == 0) {
        float L = 0.0f;
        #pragma unroll
        for (int w = 0; w < NW; ++w) L += red[w];
        g_part_ml[2 * pbase + 0] = M;
        g_part_ml[2 * pbase + 1] = L;
    }
}

// ---------------------------------------------------------------------------
// Kernel 2: combine NSPLIT partials per (b,h) via log-sum-exp.
// ---------------------------------------------------------------------------
__global__ __launch_bounds__(D)
void pa_combine_kernel(float* __restrict__ out)
{
    const int bh = blockIdx.x;
    const int d  = threadIdx.x;

    float lm[NSPLIT], ll[NSPLIT];
    float M = -3.4e38f;
    #pragma unroll
    for (int s = 0; s < NSPLIT; ++s) {
        lm[s] = g_part_ml[2 * (bh * NSPLIT + s) + 0];
        ll[s] = g_part_ml[2 * (bh * NSPLIT + s) + 1];
        M = fmaxf(M, lm[s]);
    }

    float L = 0.0f, o = 0.0f;
    #pragma unroll
    for (int s = 0; s < NSPLIT; ++s) {
        const float f = __expf(lm[s] - M);
        L += ll[s] * f;
        o += g_part_acc[(bh * NSPLIT + s) * D + d] * f;
    }
    out[bh * D + d] = o / L;
}

extern "C" void kernel_launch(void* const* d_in, const int* in_sizes, int n_in,
                              void* d_out, int out_size)
{
    const float* q  = (const float*)d_in[0];
    const float* kc = (const float*)d_in[1];
    const float* vc = (const float*)d_in[2];
    const int*   bt = (const int*)d_in[3];
    const int*   cl = (const int*)d_in[4];
    float* out = (float*)d_out;

    pa_split_kernel<<<B * H * NSPLIT, THREADS>>>(q, kc, vc, bt, cl);
    pa_combine_kernel<<<B * H, D>>>(out);
}